// round 12
// baseline (speedup 1.0000x reference)
#include <cuda_runtime.h>

#define C 38
#define PAD_IDX 0
#define O_IDX 1
#define TILE 256
#define ROWS 257
#define TDIM 288          // 8 primary warps + 1 boundary warp
#define NWARPS 9
#define F2 19             // 38 floats = 19 float2
#define NPAIR 18          // canonical invalid columns
#define LOG2E 1.44269504088896f

// ---------------- device-global scratch (no allocations allowed) ----------------
__device__ int g_ncols;
__device__ int g_col[C], g_k[C], g_off[C];
__device__ float g_base[C], g_sign[C];
__device__ unsigned char g_idx[C * C];
__device__ int g_spec2;         // canonical BIO structure -> fused fast path
__device__ float g_ubase, g_usign;
__device__ float g_partials[8 * 2048];
__device__ unsigned int g_ticket;

__device__ __forceinline__ void cp_async8(unsigned int dst, const void* src) {
    asm volatile("cp.async.ca.shared.global [%0], [%1], 8;" :: "r"(dst), "l"(src));
}

// ---------------- kernel A: build compact transition descriptor ----------------
__global__ void build_desc_kernel(const float* __restrict__ mask) {
    __shared__ float s_mask[C * C];
    __shared__ int s_n[C];
    __shared__ int s_slot[C], s_woff[C];
    const int tid = threadIdx.x;

    for (int i = tid; i < C * C; i += blockDim.x) s_mask[i] = mask[i];
    __syncthreads();

    if (tid < C) {
        int n = 0;
        for (int p = 0; p < C; p++)
            if (s_mask[p * C + tid] < 0.5f) n++;
        s_n[tid] = n;
    }
    __syncthreads();

    if (tid == 0) {
        int ncols = 0, off = 0;
        for (int c = 0; c < C; c++) {
            int n = s_n[c];
            if (n == 0) { s_slot[c] = -1; continue; }
            s_slot[c] = ncols;
            s_woff[c] = off;
            g_col[ncols] = c;
            g_off[ncols] = off;
            if (2 * n <= C) {
                g_base[ncols] = 0.f; g_sign[ncols] = 1.f; g_k[ncols] = n; off += n;
            } else {
                g_base[ncols] = 1.f; g_sign[ncols] = -1.f; g_k[ncols] = C - n; off += C - n;
            }
            ncols++;
        }
        g_ncols = ncols;
        g_ticket = 0u;
    }
    __syncthreads();

    if (tid < C && s_slot[tid] >= 0) {
        const int c = tid;
        const int n = s_n[c];
        int off = s_woff[c];
        if (2 * n <= C) {
            for (int p = 0; p < C; p++)
                if (s_mask[p * C + c] < 0.5f) g_idx[off++] = (unsigned char)p;
        } else {
            for (int p = 0; p < C; p++)
                if (s_mask[p * C + c] >= 0.5f) g_idx[off++] = (unsigned char)p;
        }
    }
    __syncthreads();

    // canonical detection: ncols == NPAIR, uniform k==2/base/sign, slot j has
    // complement pair {2(j+1), 2(j+1)+1} with column 2(j+1)+1.
    if (tid == 0) {
        const int nc = g_ncols;
        int spec = (nc == NPAIR) ? 1 : 0;
        for (int j = 0; j < nc && spec; j++) {
            const int off = g_off[j];
            if (g_k[j] != 2 || g_base[j] != g_base[0] || g_sign[j] != g_sign[0])
                spec = 0;
            else {
                const int i0 = g_idx[off], i1 = g_idx[off + 1];
                if (i0 != 2 * (j + 1) || i1 != i0 + 1 || g_col[j] != i0 + 1)
                    spec = 0;
            }
        }
        if (nc > 0) { g_ubase = g_base[0]; g_usign = g_sign[0]; }
        g_spec2 = spec;
    }
}

// ---------------- kernel B: main fused loss kernel ----------------
__global__ void __launch_bounds__(TDIM, 5) ner_main_kernel(
    const float* __restrict__ logits, const int* __restrict__ labels,
    float* __restrict__ out, int T, int nblocks) {
    __shared__ float2 sm2[ROWS * F2];            // staged logits tile (read-only in fast path)
    __shared__ float s_ps[8][F2];                // lane-31 pairsum stash (k=1..18)
    __shared__ float s_sinv[8];
    __shared__ unsigned char s_sval[8];
    __shared__ float s_red[NWARPS * 8];
    __shared__ int s_islast;
    __shared__ float s_invs[ROWS];               // fallback only
    __shared__ unsigned char s_valid[ROWS];      // fallback only

    const int tid = threadIdx.x;
    const int warp = tid >> 5, lane = tid & 31;
    const int chunks = T / TILE;
    const int b = blockIdx.x / chunks;
    const int chunk = blockIdx.x % chunks;
    const int start = chunk * TILE;
    const bool has_prev = (chunk > 0);
    const int spec2 = g_spec2;
    const float ubase = g_ubase, usign = g_usign;
    const unsigned full = 0xffffffffu;

    // cp.async staging: shared tile is a packed image of global (stride == C)
    {
        const int row0 = has_prev ? 0 : 1;
        const int nrows = has_prev ? ROWS : TILE;
        const float2* g2 = (const float2*)(
            logits + ((long long)b * T + start - (has_prev ? 1 : 0)) * (long long)C);
        unsigned int sbase = (unsigned int)__cvta_generic_to_shared(sm2 + row0 * F2);
        const int total2 = nrows * F2;
        for (int i = tid; i < total2; i += TDIM)
            cp_async8(sbase + (unsigned int)i * 8u, g2 + i);
        asm volatile("cp.async.commit_group;");
    }

    // row assignment + label prefetch while the tile is in flight
    // fast path: warps 0..7 own rows 32w+lane; warp 8 lanes 1..8 own rows 32*lane
    int prow;
    if (spec2)
        prow = (warp < 8) ? (warp * 32 + lane)
                          : ((lane >= 1 && lane <= 8) ? lane * 32 : -1);
    else
        prow = (tid < ROWS) ? tid : -1;
    const bool row_ok = (prow >= 0) && (has_prev || prow >= 1);
    int label = PAD_IDX;
    if (row_ok) label = labels[(long long)b * T + (start - 1 + prow)];

    asm volatile("cp.async.wait_group 0;");
    __syncthreads();

    float ce = 0.f, miss = 0.f, fp = 0.f, trans = 0.f;
    bool ce_f = false, miss_f = false, fp_f = false, trans_f = false;

    if (spec2) {
        // ================= fused fast path =================
        const bool is_primary = (warp < 8);
        const int row_safe = (prow >= 0) ? prow : 0;
        const bool valid = row_ok && (label != PAD_IDX);
        const float2* row2 = sm2 + row_safe * F2;
        const float gold_l = ((const float*)row2)[label];

        float2 v = row2[0];
        const float e00 = exp2f(v.x * LOG2E);
        const float eO  = exp2f(v.y * LOG2E);                // O_IDX == 1
        float s0 = e00 + eO, s1 = 0.f, A = 0.f, B = 0.f;
        const bool stash = is_primary && (lane == 31);
        #pragma unroll
        for (int k = 1; k < F2; k++) {
            v = row2[k];
            const float e0 = exp2f(v.x * LOG2E);
            const float e1 = exp2f(v.y * LOG2E);
            const float ps = e0 + e1;
            if (k & 1) s1 += ps; else s0 += ps;
            if (stash) s_ps[warp][k] = ps;
            const float e1n = __shfl_down_sync(full, e1, 1); // eodd of lane+1's row
            A += e1n;
            B = fmaf(e1n, ps, B);
        }
        const float s = s0 + s1;
        const float invs = 1.f / s;
        if (stash) { s_sinv[warp] = invs; s_sval[warp] = valid ? 1 : 0; }

        const unsigned vb = __ballot_sync(full, valid);
        const float invc = __shfl_down_sync(full, invs, 1);

        // CE/miss/fp: each token row owned exactly once
        const bool owns_ce = valid && (is_primary ? (prow >= 1) : (lane == 8));
        if (owns_ce) {
            ce = __logf(s) - gold_l; ce_f = true;
            const float p_o = eO * invs;
            if (label == O_IDX) { fp = -__logf(fmaxf(p_o, 1e-8f)); fp_f = true; }
            else { miss = -__logf(fmaxf(1.f - p_o, 1e-8f)); miss_f = true; }
        }
        // interior pairs: lane l owns (row, row+1), data from lane l+1 via shuffle
        if (is_primary && lane < 31 && valid && ((vb >> (lane + 1)) & 1u)) {
            trans = invc * fmaf(usign * invs, B, ubase * A);
            trans_f = true;
        }
        __syncthreads();   // stash (ps/invs/valid) -> warp 8
        // boundary pairs (32m-1, 32m), m=1..8: warp 8 owns them
        if (!is_primary && lane >= 1 && lane <= 8 && valid && s_sval[lane - 1]) {
            float A2 = 0.f, B2 = 0.f;
            #pragma unroll
            for (int k = 1; k < F2; k++) {
                const float e1 = exp2f(row2[k].y * LOG2E);
                A2 += e1;
                B2 = fmaf(e1, s_ps[lane - 1][k], B2);
            }
            trans = invs * fmaf(usign * s_sinv[lane - 1], B2, ubase * A2);
            trans_f = true;
        }
    } else {
        // ================= general fallback =================
        if (!has_prev && tid == 0) s_valid[0] = 0;
        if (row_ok) {
            const int r = prow;
            float2* row2 = sm2 + r * F2;
            s_valid[r] = (unsigned char)(label != PAD_IDX);
            const float gold_l = ((const float*)row2)[label];
            float2 v = row2[0];
            const float e0a = exp2f(v.x * LOG2E);
            const float eO = exp2f(v.y * LOG2E);
            float s0 = e0a + eO, s1 = 0.f;
            #pragma unroll
            for (int k = 1; k < F2; k++) {
                v = row2[k];
                const float e0 = exp2f(v.x * LOG2E);
                const float e1 = exp2f(v.y * LOG2E);
                if (k & 1) s1 += e0 + e1; else s0 += e0 + e1;
                row2[k] = make_float2(e0, e1);
            }
            row2[0] = make_float2(e0a, eO);
            const float s = s0 + s1;
            const float invs = 1.f / s;
            s_invs[r] = invs;
            if (r >= 1 && label != PAD_IDX) {
                ce = (__logf(s) - gold_l); ce_f = true;
                const float p_o = eO * invs;
                if (label == O_IDX) { fp = -__logf(fmaxf(p_o, 1e-8f)); fp_f = true; }
                else { miss = -__logf(fmaxf(1.f - p_o, 1e-8f)); miss_f = true; }
            }
        }
        __syncthreads();
        if (tid < TILE) {
            const int t = tid;
            if (s_valid[t] && s_valid[t + 1]) {
                const float* pp = (const float*)(sm2 + t * F2);
                const float* pc = (const float*)(sm2 + (t + 1) * F2);
                const float invp = s_invs[t];
                float msum = 0.f;
                const int nc = g_ncols;
                for (int j = 0; j < nc; j++) {
                    const int off = g_off[j];
                    const int kk = g_k[j];
                    float acc = 0.f;
                    for (int i = 0; i < kk; i++) acc += pp[g_idx[off + i]];
                    const float term = fmaf(g_sign[j] * invp, acc, g_base[j]);
                    msum = fmaf(pc[g_col[j]], term, msum);
                }
                trans = msum * s_invs[t + 1];
                trans_f = true;
            }
        }
    }

    // -------- block reduction: 4 float sums + 4 popc counts --------
    const unsigned b_ce = __ballot_sync(full, ce_f);
    const unsigned b_ms = __ballot_sync(full, miss_f);
    const unsigned b_fp = __ballot_sync(full, fp_f);
    const unsigned b_tr = __ballot_sync(full, trans_f);
    float sums[4] = {ce, miss, fp, trans};
    #pragma unroll
    for (int k = 0; k < 4; k++) {
        float x = sums[k];
        #pragma unroll
        for (int o = 16; o > 0; o >>= 1) x += __shfl_down_sync(full, x, o);
        sums[k] = x;
    }
    if (lane == 0) {
        s_red[warp * 8 + 0] = sums[0];
        s_red[warp * 8 + 1] = (float)__popc(b_ce);
        s_red[warp * 8 + 2] = sums[1];
        s_red[warp * 8 + 3] = (float)__popc(b_ms);
        s_red[warp * 8 + 4] = sums[2];
        s_red[warp * 8 + 5] = (float)__popc(b_fp);
        s_red[warp * 8 + 6] = sums[3];
        s_red[warp * 8 + 7] = (float)__popc(b_tr);
    }
    __syncthreads();
    if (tid == 0) {
        #pragma unroll
        for (int k = 0; k < 8; k++) {
            float a = 0.f;
            #pragma unroll
            for (int w = 0; w < NWARPS; w++) a += s_red[w * 8 + k];
            g_partials[blockIdx.x * 8 + k] = a;
        }
        __threadfence();
        unsigned int t = atomicAdd(&g_ticket, 1u);
        s_islast = (t == (unsigned int)(nblocks - 1)) ? 1 : 0;
    }
    __syncthreads();

    // -------- last block: deterministic final reduction + output --------
    if (s_islast) {
        float acc[8] = {0.f, 0.f, 0.f, 0.f, 0.f, 0.f, 0.f, 0.f};
        for (int i = tid; i < nblocks; i += TDIM) {
            #pragma unroll
            for (int k = 0; k < 8; k++) acc[k] += g_partials[i * 8 + k];
        }
        #pragma unroll
        for (int k = 0; k < 8; k++) {
            float x = acc[k];
            #pragma unroll
            for (int o = 16; o > 0; o >>= 1) x += __shfl_down_sync(full, x, o);
            acc[k] = x;
        }
        if (lane == 0) {
            #pragma unroll
            for (int k = 0; k < 8; k++) s_red[warp * 8 + k] = acc[k];
        }
        __syncthreads();
        if (tid == 0) {
            float r[8];
            #pragma unroll
            for (int k = 0; k < 8; k++) {
                float a = 0.f;
                #pragma unroll
                for (int w = 0; w < NWARPS; w++) a += s_red[w * 8 + k];
                r[k] = a;
            }
            const float cem   = r[0] / fmaxf(r[1], 1.f);
            const float missm = r[2] / fmaxf(r[3], 1.f);
            const float fpm   = r[4] / fmaxf(r[5], 1.f);
            const float trm   = r[6] / fmaxf(r[7], 1.f);
            out[0] = cem + 1.2f * missm + 1.0f * fpm + 0.8f * trm;
        }
    }
}

// ---------------- launch ----------------
extern "C" void kernel_launch(void* const* d_in, const int* in_sizes, int n_in,
                              void* d_out, int out_size) {
    const float* logits = (const float*)d_in[0];
    const int* labels = (const int*)d_in[1];
    const float* mask = (const float*)d_in[2];

    const int BT = in_sizes[1];
    const int T = 4096;
    const int B = BT / T;
    const int chunks = T / TILE;
    const int nblocks = B * chunks;   // 2048

    build_desc_kernel<<<1, 256>>>(mask);
    ner_main_kernel<<<nblocks, TDIM>>>(logits, labels, (float*)d_out, T, nblocks);
}

// round 13
// speedup vs baseline: 1.0534x; 1.0534x over previous
#include <cuda_runtime.h>

#define C 38
#define PAD_IDX 0
#define O_IDX 1
#define TILE 256
#define ROWS 257
#define TDIM 288          // warps 0..7: 32 rows each; warp 8: row 256 + boundary pairs
#define NWARPS 9
#define F2 19             // 38 floats = 19 float2
#define NPAIR 18
#define LOG2E 1.44269504088896f

// ---------------- device-global scratch (no allocations allowed) ----------------
__device__ int g_ncols;
__device__ int g_col[C], g_k[C], g_off[C];
__device__ float g_base[C], g_sign[C];
__device__ unsigned char g_idx[C * C];
__device__ int g_spec2;         // canonical BIO structure -> fused fast path
__device__ float g_ubase, g_usign;
__device__ float g_partials[8 * 2048];
__device__ unsigned int g_ticket;

__device__ __forceinline__ void cp_async8(unsigned int dst, const void* src) {
    asm volatile("cp.async.ca.shared.global [%0], [%1], 8;" :: "r"(dst), "l"(src));
}
// packed (v.x*log2e, v.y*log2e) in one f32x2 mul; unpack is a register-pair rename
__device__ __forceinline__ float2 mul2_log2e(const float2* p) {
    unsigned long long v = *(const unsigned long long*)p;
    unsigned long long r;
    asm("mul.rn.f32x2 %0, %1, %2;" : "=l"(r)
        : "l"(v), "l"(0x3FB8AA3B3FB8AA3BULL));
    float2 o;
    asm("mov.b64 {%0,%1}, %2;" : "=f"(o.x), "=f"(o.y) : "l"(r));
    return o;
}

// ---------------- kernel A: build compact transition descriptor ----------------
__global__ void build_desc_kernel(const float* __restrict__ mask) {
    __shared__ float s_mask[C * C];
    __shared__ int s_n[C];
    __shared__ int s_slot[C], s_woff[C];
    const int tid = threadIdx.x;

    for (int i = tid; i < C * C; i += blockDim.x) s_mask[i] = mask[i];
    __syncthreads();

    if (tid < C) {
        int n = 0;
        for (int p = 0; p < C; p++)
            if (s_mask[p * C + tid] < 0.5f) n++;
        s_n[tid] = n;
    }
    __syncthreads();

    if (tid == 0) {
        int ncols = 0, off = 0;
        for (int c = 0; c < C; c++) {
            int n = s_n[c];
            if (n == 0) { s_slot[c] = -1; continue; }
            s_slot[c] = ncols;
            s_woff[c] = off;
            g_col[ncols] = c;
            g_off[ncols] = off;
            if (2 * n <= C) {
                g_base[ncols] = 0.f; g_sign[ncols] = 1.f; g_k[ncols] = n; off += n;
            } else {
                g_base[ncols] = 1.f; g_sign[ncols] = -1.f; g_k[ncols] = C - n; off += C - n;
            }
            ncols++;
        }
        g_ncols = ncols;
        g_ticket = 0u;
    }
    __syncthreads();

    if (tid < C && s_slot[tid] >= 0) {
        const int c = tid;
        const int n = s_n[c];
        int off = s_woff[c];
        if (2 * n <= C) {
            for (int p = 0; p < C; p++)
                if (s_mask[p * C + c] < 0.5f) g_idx[off++] = (unsigned char)p;
        } else {
            for (int p = 0; p < C; p++)
                if (s_mask[p * C + c] >= 0.5f) g_idx[off++] = (unsigned char)p;
        }
    }
    __syncthreads();

    // canonical detection: ncols == NPAIR, uniform k==2/base/sign, slot j has
    // complement pair {2(j+1), 2(j+1)+1} with column 2(j+1)+1.
    if (tid == 0) {
        const int nc = g_ncols;
        int spec = (nc == NPAIR) ? 1 : 0;
        for (int j = 0; j < nc && spec; j++) {
            const int off = g_off[j];
            if (g_k[j] != 2 || g_base[j] != g_base[0] || g_sign[j] != g_sign[0])
                spec = 0;
            else {
                const int i0 = g_idx[off], i1 = g_idx[off + 1];
                if (i0 != 2 * (j + 1) || i1 != i0 + 1 || g_col[j] != i0 + 1)
                    spec = 0;
            }
        }
        if (nc > 0) { g_ubase = g_base[0]; g_usign = g_sign[0]; }
        g_spec2 = spec;
    }
}

// ---------------- kernel B: main fused loss kernel ----------------
__global__ void __launch_bounds__(TDIM, 5) ner_main_kernel(
    const float* __restrict__ logits, const int* __restrict__ labels,
    float* __restrict__ out, int T, int nblocks) {
    __shared__ float2 sm2[ROWS * F2];            // staged logits (read-only, fast path)
    __shared__ float s_tail_ps[8][NPAIR];        // lane-31 pairsums per primary warp
    __shared__ float s_tail_inv[8];
    __shared__ unsigned char s_tail_val[8];
    __shared__ float s_head_inv[9];              // lane-0 invs (rows 32m, 256)
    __shared__ unsigned char s_head_val[9];
    __shared__ float s_red[NWARPS * 8];
    __shared__ int s_islast;
    __shared__ float s_invs[ROWS];               // fallback only
    __shared__ unsigned char s_valid[ROWS];      // fallback only

    const int tid = threadIdx.x;
    const int warp = tid >> 5, lane = tid & 31;
    const int chunks = T / TILE;
    const int b = blockIdx.x / chunks;
    const int chunk = blockIdx.x % chunks;
    const int start = chunk * TILE;
    const bool has_prev = (chunk > 0);
    const int spec2 = g_spec2;
    const float ubase = g_ubase, usign = g_usign;
    const unsigned full = 0xffffffffu;
    const unsigned sbase = (unsigned)__cvta_generic_to_shared(sm2);

    // ---- per-warp staging: warp w copies ONLY its own rows; no block barrier ----
    if (warp < 8) {
        const int rb = 32 * warp + ((warp == 0 && !has_prev) ? 1 : 0);
        const int n = (32 * warp + 32 - rb) * F2;    // 608, or 589 for warp0/!prev
        const float2* src = (const float2*)(
            logits + ((long long)b * T + start - 1 + rb) * (long long)C);
        const unsigned dst = sbase + (unsigned)(rb * F2) * 8u;
        if (n == 32 * F2) {
            #pragma unroll
            for (int j = 0; j < F2; j++)
                cp_async8(dst + (unsigned)(lane + 32 * j) * 8u, src + lane + 32 * j);
        } else {
            for (int i = lane; i < n; i += 32)
                cp_async8(dst + (unsigned)i * 8u, src + i);
        }
    } else {
        const float2* src = (const float2*)(
            logits + ((long long)b * T + start - 1 + 256) * (long long)C);
        if (lane < F2)
            cp_async8(sbase + (unsigned)(256 * F2 + lane) * 8u, src + lane);
    }
    asm volatile("cp.async.commit_group;");

    // row assignment + label prefetch while this warp's copy is in flight
    int prow;
    if (spec2) prow = (warp < 8) ? (warp * 32 + lane) : ((lane == 0) ? 256 : -1);
    else       prow = (tid < ROWS) ? tid : -1;
    const bool row_ok = (prow >= 0) && (has_prev || prow >= 1);
    int label = PAD_IDX;
    if (row_ok) label = labels[(long long)b * T + (start - 1 + prow)];

    asm volatile("cp.async.wait_group 0;");
    __syncwarp();                                  // own rows visible warp-wide

    float ce = 0.f, miss = 0.f, fp = 0.f, trans = 0.f;
    bool ce_f = false, miss_f = false, fp_f = false, trans_f = false;

    if (spec2) {
        // ================= fused fast path =================
        if (warp < 8) {
            const int r = prow;                    // in this warp's staged range
            const float2* row2 = sm2 + r * F2;
            const bool valid = row_ok && (label != PAD_IDX);
            const float gold_l = ((const float*)row2)[label];

            float2 e = mul2_log2e(row2);
            const float e00 = exp2f(e.x);
            const float eO  = exp2f(e.y);          // O_IDX == 1
            float s0 = e00 + eO, s1 = 0.f, A = 0.f, B = 0.f;
            const bool tail = (lane == 31);
            #pragma unroll
            for (int k = 1; k < F2; k++) {
                e = mul2_log2e(row2 + k);
                const float e0 = exp2f(e.x);
                const float e1 = exp2f(e.y);
                const float ps = e0 + e1;
                if (k & 1) s1 += ps; else s0 += ps;
                if (tail) s_tail_ps[warp][k - 1] = ps;
                const float e1n = __shfl_down_sync(full, e1, 1);
                A += e1n;
                B = fmaf(e1n, ps, B);
            }
            const float s = s0 + s1;
            const float invs = 1.f / s;
            if (tail)      { s_tail_inv[warp] = invs; s_tail_val[warp] = valid; }
            if (lane == 0) { s_head_inv[warp] = invs; s_head_val[warp] = valid; }

            const unsigned vb = __ballot_sync(full, valid);
            const float invc = __shfl_down_sync(full, invs, 1);

            if (valid && r >= 1) {                 // CE for tokens start..start+254
                ce = __logf(s) - gold_l; ce_f = true;
                const float p_o = eO * invs;
                if (label == O_IDX) { fp = -__logf(fmaxf(p_o, 1e-8f)); fp_f = true; }
                else { miss = -__logf(fmaxf(1.f - p_o, 1e-8f)); miss_f = true; }
            }
            if (lane < 31 && valid && ((vb >> (lane + 1)) & 1u)) {
                trans = invc * fmaf(usign * invs, B, ubase * A);
                trans_f = true;
            }
        } else if (lane == 0) {
            // warp 8 lane 0: row 256 softmax (token start+255) — serial
            const float2* row2 = sm2 + 256 * F2;
            const bool valid = (label != PAD_IDX);
            const float gold_l = ((const float*)row2)[label];
            float s0 = 0.f, s1 = 0.f, eO = 0.f;
            #pragma unroll
            for (int k = 0; k < F2; k++) {
                float2 e = mul2_log2e(row2 + k);
                const float a0 = exp2f(e.x), a1 = exp2f(e.y);
                if (k == 0) eO = a1;
                s0 += a0; s1 += a1;
            }
            const float s = s0 + s1;
            const float invs = 1.f / s;
            s_head_inv[8] = invs; s_head_val[8] = valid;
            if (valid) {
                ce = __logf(s) - gold_l; ce_f = true;
                const float p_o = eO * invs;
                if (label == O_IDX) { fp = -__logf(fmaxf(p_o, 1e-8f)); fp_f = true; }
                else { miss = -__logf(fmaxf(1.f - p_o, 1e-8f)); miss_f = true; }
            }
        }
        __syncthreads();                           // stashes + all staged rows visible
        // boundary pairs (32m-1, 32m), m=1..8 — warp 8 lanes 1..8
        if (warp == 8 && lane >= 1 && lane <= 8) {
            const int m = lane;
            if (s_head_val[m] && s_tail_val[m - 1]) {
                const float2* r2 = sm2 + (32 * m) * F2;   // row 32m (or 256)
                float A2 = 0.f, B2 = 0.f;
                #pragma unroll
                for (int k = 1; k < F2; k++) {
                    float2 e = mul2_log2e(r2 + k);
                    const float e1 = exp2f(e.y);
                    A2 += e1;
                    B2 = fmaf(e1, s_tail_ps[m - 1][k - 1], B2);
                }
                trans = s_head_inv[m] *
                        fmaf(usign * s_tail_inv[m - 1], B2, ubase * A2);
                trans_f = true;
            }
        }
    } else {
        // ================= general fallback =================
        if (!has_prev && tid == 0) s_valid[0] = 0;
        if (row_ok) {
            const int r = prow;                    // own warp staged this row
            float2* row2 = sm2 + r * F2;
            s_valid[r] = (unsigned char)(label != PAD_IDX);
            const float gold_l = ((const float*)row2)[label];
            float2 v = row2[0];
            const float e0a = exp2f(v.x * LOG2E);
            const float eO = exp2f(v.y * LOG2E);
            float s0 = e0a + eO, s1 = 0.f;
            #pragma unroll
            for (int k = 1; k < F2; k++) {
                v = row2[k];
                const float e0 = exp2f(v.x * LOG2E);
                const float e1 = exp2f(v.y * LOG2E);
                if (k & 1) s1 += e0 + e1; else s0 += e0 + e1;
                row2[k] = make_float2(e0, e1);
            }
            row2[0] = make_float2(e0a, eO);
            const float s = s0 + s1;
            const float invs = 1.f / s;
            s_invs[r] = invs;
            if (r >= 1 && label != PAD_IDX) {
                ce = (__logf(s) - gold_l); ce_f = true;
                const float p_o = eO * invs;
                if (label == O_IDX) { fp = -__logf(fmaxf(p_o, 1e-8f)); fp_f = true; }
                else { miss = -__logf(fmaxf(1.f - p_o, 1e-8f)); miss_f = true; }
            }
        }
        __syncthreads();
        if (tid < TILE) {
            const int t = tid;
            if (s_valid[t] && s_valid[t + 1]) {
                const float* pp = (const float*)(sm2 + t * F2);
                const float* pc = (const float*)(sm2 + (t + 1) * F2);
                const float invp = s_invs[t];
                float msum = 0.f;
                const int nc = g_ncols;
                for (int j = 0; j < nc; j++) {
                    const int off = g_off[j];
                    const int kk = g_k[j];
                    float acc = 0.f;
                    for (int i = 0; i < kk; i++) acc += pp[g_idx[off + i]];
                    const float term = fmaf(g_sign[j] * invp, acc, g_base[j]);
                    msum = fmaf(pc[g_col[j]], term, msum);
                }
                trans = msum * s_invs[t + 1];
                trans_f = true;
            }
        }
    }

    // -------- block reduction: 4 float sums + 4 popc counts --------
    const unsigned b_ce = __ballot_sync(full, ce_f);
    const unsigned b_ms = __ballot_sync(full, miss_f);
    const unsigned b_fp = __ballot_sync(full, fp_f);
    const unsigned b_tr = __ballot_sync(full, trans_f);
    float sums[4] = {ce, miss, fp, trans};
    #pragma unroll
    for (int k = 0; k < 4; k++) {
        float x = sums[k];
        #pragma unroll
        for (int o = 16; o > 0; o >>= 1) x += __shfl_down_sync(full, x, o);
        sums[k] = x;
    }
    if (lane == 0) {
        s_red[warp * 8 + 0] = sums[0];
        s_red[warp * 8 + 1] = (float)__popc(b_ce);
        s_red[warp * 8 + 2] = sums[1];
        s_red[warp * 8 + 3] = (float)__popc(b_ms);
        s_red[warp * 8 + 4] = sums[2];
        s_red[warp * 8 + 5] = (float)__popc(b_fp);
        s_red[warp * 8 + 6] = sums[3];
        s_red[warp * 8 + 7] = (float)__popc(b_tr);
    }
    __syncthreads();
    if (tid == 0) {
        #pragma unroll
        for (int k = 0; k < 8; k++) {
            float a = 0.f;
            #pragma unroll
            for (int w = 0; w < NWARPS; w++) a += s_red[w * 8 + k];
            g_partials[blockIdx.x * 8 + k] = a;
        }
        __threadfence();
        unsigned int t = atomicAdd(&g_ticket, 1u);
        s_islast = (t == (unsigned int)(nblocks - 1)) ? 1 : 0;
    }
    __syncthreads();

    // -------- last block: deterministic final reduction + output --------
    if (s_islast) {
        float acc[8] = {0.f, 0.f, 0.f, 0.f, 0.f, 0.f, 0.f, 0.f};
        for (int i = tid; i < nblocks; i += TDIM) {
            #pragma unroll
            for (int k = 0; k < 8; k++) acc[k] += g_partials[i * 8 + k];
        }
        #pragma unroll
        for (int k = 0; k < 8; k++) {
            float x = acc[k];
            #pragma unroll
            for (int o = 16; o > 0; o >>= 1) x += __shfl_down_sync(full, x, o);
            acc[k] = x;
        }
        if (lane == 0) {
            #pragma unroll
            for (int k = 0; k < 8; k++) s_red[warp * 8 + k] = acc[k];
        }
        __syncthreads();
        if (tid == 0) {
            float r[8];
            #pragma unroll
            for (int k = 0; k < 8; k++) {
                float a = 0.f;
                #pragma unroll
                for (int w = 0; w < NWARPS; w++) a += s_red[w * 8 + k];
                r[k] = a;
            }
            const float cem   = r[0] / fmaxf(r[1], 1.f);
            const float missm = r[2] / fmaxf(r[3], 1.f);
            const float fpm   = r[4] / fmaxf(r[5], 1.f);
            const float trm   = r[6] / fmaxf(r[7], 1.f);
            out[0] = cem + 1.2f * missm + 1.0f * fpm + 0.8f * trm;
        }
    }
}

// ---------------- launch ----------------
extern "C" void kernel_launch(void* const* d_in, const int* in_sizes, int n_in,
                              void* d_out, int out_size) {
    const float* logits = (const float*)d_in[0];
    const int* labels = (const int*)d_in[1];
    const float* mask = (const float*)d_in[2];

    const int BT = in_sizes[1];
    const int T = 4096;
    const int B = BT / T;
    const int chunks = T / TILE;
    const int nblocks = B * chunks;   // 2048

    build_desc_kernel<<<1, 256>>>(mask);
    ner_main_kernel<<<nblocks, TDIM>>>(logits, labels, (float*)d_out, T, nblocks);
}

// round 14
// speedup vs baseline: 1.1311x; 1.0738x over previous
#include <cuda_runtime.h>

#define C 38
#define PAD_IDX 0
#define O_IDX 1
#define TILE 256
#define ROWS 257
#define TDIM 288          // warps 0..7: 32 rows each; warp 8: row 256 + boundary pairs
#define NWARPS 9
#define F2 19             // 38 floats = 19 float2
#define NPAIR 18
#define LOG2E 1.44269504088896f

// ---------------- device-global scratch (no allocations allowed) ----------------
__device__ int g_ncols;
__device__ int g_col[C], g_k[C], g_off[C];
__device__ float g_base[C], g_sign[C];
__device__ unsigned char g_idx[C * C];
__device__ int g_spec2;         // canonical BIO structure -> fused fast path
__device__ float g_ubase, g_usign;
__device__ float g_partials[8 * 2048];
__device__ unsigned int g_ticket;

// packed (v.x*log2e, v.y*log2e) in one f32x2 mul
__device__ __forceinline__ float2 mul2_log2e(const float2* p) {
    unsigned long long v = *(const unsigned long long*)p;
    unsigned long long r;
    asm("mul.rn.f32x2 %0, %1, %2;" : "=l"(r)
        : "l"(v), "l"(0x3FB8AA3B3FB8AA3BULL));
    float2 o;
    asm("mov.b64 {%0,%1}, %2;" : "=f"(o.x), "=f"(o.y) : "l"(r));
    return o;
}

// ---------------- kernel A: build compact transition descriptor ----------------
__global__ void build_desc_kernel(const float* __restrict__ mask) {
    __shared__ float s_mask[C * C];
    __shared__ int s_n[C];
    __shared__ int s_slot[C], s_woff[C];
    const int tid = threadIdx.x;

    for (int i = tid; i < C * C; i += blockDim.x) s_mask[i] = mask[i];
    __syncthreads();

    if (tid < C) {
        int n = 0;
        for (int p = 0; p < C; p++)
            if (s_mask[p * C + tid] < 0.5f) n++;
        s_n[tid] = n;
    }
    __syncthreads();

    if (tid == 0) {
        int ncols = 0, off = 0;
        for (int c = 0; c < C; c++) {
            int n = s_n[c];
            if (n == 0) { s_slot[c] = -1; continue; }
            s_slot[c] = ncols;
            s_woff[c] = off;
            g_col[ncols] = c;
            g_off[ncols] = off;
            if (2 * n <= C) {
                g_base[ncols] = 0.f; g_sign[ncols] = 1.f; g_k[ncols] = n; off += n;
            } else {
                g_base[ncols] = 1.f; g_sign[ncols] = -1.f; g_k[ncols] = C - n; off += C - n;
            }
            ncols++;
        }
        g_ncols = ncols;
        g_ticket = 0u;
    }
    __syncthreads();

    if (tid < C && s_slot[tid] >= 0) {
        const int c = tid;
        const int n = s_n[c];
        int off = s_woff[c];
        if (2 * n <= C) {
            for (int p = 0; p < C; p++)
                if (s_mask[p * C + c] < 0.5f) g_idx[off++] = (unsigned char)p;
        } else {
            for (int p = 0; p < C; p++)
                if (s_mask[p * C + c] >= 0.5f) g_idx[off++] = (unsigned char)p;
        }
    }
    __syncthreads();

    // canonical detection: ncols == NPAIR, uniform k==2/base/sign, slot j has
    // complement pair {2(j+1), 2(j+1)+1} with column 2(j+1)+1.
    if (tid == 0) {
        const int nc = g_ncols;
        int spec = (nc == NPAIR) ? 1 : 0;
        for (int j = 0; j < nc && spec; j++) {
            const int off = g_off[j];
            if (g_k[j] != 2 || g_base[j] != g_base[0] || g_sign[j] != g_sign[0])
                spec = 0;
            else {
                const int i0 = g_idx[off], i1 = g_idx[off + 1];
                if (i0 != 2 * (j + 1) || i1 != i0 + 1 || g_col[j] != i0 + 1)
                    spec = 0;
            }
        }
        if (nc > 0) { g_ubase = g_base[0]; g_usign = g_sign[0]; }
        g_spec2 = spec;
    }
}

// ---------------- kernel B: main fused loss kernel ----------------
__global__ void __launch_bounds__(TDIM, 5) ner_main_kernel(
    const float* __restrict__ logits, const int* __restrict__ labels,
    float* __restrict__ out, int T, int nblocks) {
    __shared__ __align__(16) float2 sm2[ROWS * F2 + 2];  // +2 f2: front pad + overrun
    __shared__ __align__(8) unsigned long long s_mbar;
    __shared__ float s_tail_ps[8][NPAIR];        // lane-31 pairsums per primary warp
    __shared__ float s_tail_inv[8];
    __shared__ unsigned char s_tail_val[8];
    __shared__ float s_head_inv[9];              // lane-0 invs (rows 32m, 256)
    __shared__ unsigned char s_head_val[9];
    __shared__ float s_red[NWARPS * 8];
    __shared__ int s_islast;
    __shared__ float s_invs[ROWS];               // fallback only
    __shared__ unsigned char s_valid[ROWS];      // fallback only

    const int tid = threadIdx.x;
    const int warp = tid >> 5, lane = tid & 31;
    const int chunks = T / TILE;
    const int b = blockIdx.x / chunks;
    const int chunk = blockIdx.x % chunks;
    const int start = chunk * TILE;
    const bool has_prev = (chunk > 0);
    const int spec2 = g_spec2;
    const float ubase = g_ubase, usign = g_usign;
    const unsigned full = 0xffffffffu;

    // ---- single bulk DMA stages the whole contiguous tile ----
    const int row0 = has_prev ? 0 : 1;           // first staged logical row
    const long long row0g = (long long)b * T + start - (has_prev ? 1 : 0);
    const char* gsrc = (const char*)(logits + row0g * (long long)C);
    const int pad = (int)((unsigned long long)gsrc & 15ull);        // 0 or 8
    const int nrows = has_prev ? ROWS : TILE;
    const unsigned size = (unsigned)((pad + nrows * (C * 4) + 15) & ~15);
    const unsigned mb = (unsigned)__cvta_generic_to_shared(&s_mbar);
    const unsigned dst = (unsigned)__cvta_generic_to_shared(sm2);

    if (tid == 0)
        asm volatile("mbarrier.init.shared.b64 [%0], 1;" :: "r"(mb) : "memory");
    __syncthreads();
    if (tid == 0) {
        asm volatile("mbarrier.arrive.expect_tx.shared.b64 _, [%0], %1;"
                     :: "r"(mb), "r"(size) : "memory");
        asm volatile(
            "cp.async.bulk.shared::cluster.global.mbarrier::complete_tx::bytes "
            "[%0], [%1], %2, [%3];"
            :: "r"(dst), "l"(gsrc - pad), "r"(size), "r"(mb) : "memory");
    }

    // logical row r lives at sm2 + base2 + r*F2
    const int base2 = (pad >> 3) - row0 * F2;

    // row assignment + label prefetch while the DMA is in flight
    int prow;
    if (spec2) prow = (warp < 8) ? (warp * 32 + lane) : ((lane == 0) ? 256 : -1);
    else       prow = (tid < ROWS) ? tid : -1;
    const bool row_ok = (prow >= 0) && (has_prev || prow >= 1);
    int label = PAD_IDX;
    if (row_ok) label = labels[(long long)b * T + (start - 1 + prow)];

    // wait for tile (HW-sleep try_wait, phase parity 0)
    asm volatile(
        "{\n\t.reg .pred P;\n\t"
        "W%=: mbarrier.try_wait.parity.shared.b64 P, [%0], 0;\n\t"
        "@P bra D%=;\n\t"
        "bra W%=;\n\t"
        "D%=:\n\t}" :: "r"(mb) : "memory");

    float ce = 0.f, miss = 0.f, fp = 0.f, trans = 0.f;
    bool ce_f = false, miss_f = false, fp_f = false, trans_f = false;

    if (spec2) {
        // ================= fused fast path =================
        if (warp < 8) {
            const int rs = row_ok ? prow : row0;   // staged row (safe for shuffles)
            const float2* row2 = sm2 + base2 + rs * F2;
            const bool valid = row_ok && (label != PAD_IDX);
            const float gold_l = ((const float*)row2)[label];

            float2 e = mul2_log2e(row2);
            const float e00 = exp2f(e.x);
            const float eO  = exp2f(e.y);          // O_IDX == 1
            float s0 = e00 + eO, s1 = 0.f, A = 0.f, B = 0.f;
            const bool tail = (lane == 31);
            #pragma unroll
            for (int k = 1; k < F2; k++) {
                e = mul2_log2e(row2 + k);
                const float e0 = exp2f(e.x);
                const float e1 = exp2f(e.y);
                const float ps = e0 + e1;
                if (k & 1) s1 += ps; else s0 += ps;
                if (tail) s_tail_ps[warp][k - 1] = ps;
                const float e1n = __shfl_down_sync(full, e1, 1);
                A += e1n;
                B = fmaf(e1n, ps, B);
            }
            const float s = s0 + s1;
            const float invs = 1.f / s;
            if (tail)      { s_tail_inv[warp] = invs; s_tail_val[warp] = valid; }
            if (lane == 0) { s_head_inv[warp] = invs; s_head_val[warp] = valid; }

            const unsigned vb = __ballot_sync(full, valid);
            const float invc = __shfl_down_sync(full, invs, 1);

            if (valid && prow >= 1) {              // CE for tokens start..start+254
                ce = __logf(s) - gold_l; ce_f = true;
                const float p_o = eO * invs;
                if (label == O_IDX) { fp = -__logf(fmaxf(p_o, 1e-8f)); fp_f = true; }
                else { miss = -__logf(fmaxf(1.f - p_o, 1e-8f)); miss_f = true; }
            }
            if (lane < 31 && valid && ((vb >> (lane + 1)) & 1u)) {
                trans = invc * fmaf(usign * invs, B, ubase * A);
                trans_f = true;
            }
        } else if (lane == 0) {
            // warp 8 lane 0: row 256 softmax (token start+255) — serial
            const float2* row2 = sm2 + base2 + 256 * F2;
            const bool valid = (label != PAD_IDX);
            const float gold_l = ((const float*)row2)[label];
            float s0 = 0.f, s1 = 0.f, eO = 0.f;
            #pragma unroll
            for (int k = 0; k < F2; k++) {
                float2 e = mul2_log2e(row2 + k);
                const float a0 = exp2f(e.x), a1 = exp2f(e.y);
                if (k == 0) eO = a1;
                s0 += a0; s1 += a1;
            }
            const float s = s0 + s1;
            const float invs = 1.f / s;
            s_head_inv[8] = invs; s_head_val[8] = valid;
            if (valid) {
                ce = __logf(s) - gold_l; ce_f = true;
                const float p_o = eO * invs;
                if (label == O_IDX) { fp = -__logf(fmaxf(p_o, 1e-8f)); fp_f = true; }
                else { miss = -__logf(fmaxf(1.f - p_o, 1e-8f)); miss_f = true; }
            }
        }
        __syncthreads();                           // stashes visible
        // boundary pairs (32m-1, 32m), m=1..8 — warp 8 lanes 1..8
        if (warp == 8 && lane >= 1 && lane <= 8) {
            const int m = lane;
            if (s_head_val[m] && s_tail_val[m - 1]) {
                const float2* r2 = sm2 + base2 + (32 * m) * F2;  // row 32m (or 256)
                float A2 = 0.f, B2 = 0.f;
                #pragma unroll
                for (int k = 1; k < F2; k++) {
                    float2 e = mul2_log2e(r2 + k);
                    const float e1 = exp2f(e.y);
                    A2 += e1;
                    B2 = fmaf(e1, s_tail_ps[m - 1][k - 1], B2);
                }
                trans = s_head_inv[m] *
                        fmaf(usign * s_tail_inv[m - 1], B2, ubase * A2);
                trans_f = true;
            }
        }
    } else {
        // ================= general fallback =================
        if (!has_prev && tid == 0) s_valid[0] = 0;
        if (row_ok) {
            const int r = prow;
            float2* row2 = sm2 + base2 + r * F2;
            s_valid[r] = (unsigned char)(label != PAD_IDX);
            const float gold_l = ((const float*)row2)[label];
            float2 v = row2[0];
            const float e0a = exp2f(v.x * LOG2E);
            const float eO = exp2f(v.y * LOG2E);
            float s0 = e0a + eO, s1 = 0.f;
            #pragma unroll
            for (int k = 1; k < F2; k++) {
                v = row2[k];
                const float e0 = exp2f(v.x * LOG2E);
                const float e1 = exp2f(v.y * LOG2E);
                if (k & 1) s1 += e0 + e1; else s0 += e0 + e1;
                row2[k] = make_float2(e0, e1);
            }
            row2[0] = make_float2(e0a, eO);
            const float s = s0 + s1;
            const float invs = 1.f / s;
            s_invs[r] = invs;
            if (r >= 1 && label != PAD_IDX) {
                ce = (__logf(s) - gold_l); ce_f = true;
                const float p_o = eO * invs;
                if (label == O_IDX) { fp = -__logf(fmaxf(p_o, 1e-8f)); fp_f = true; }
                else { miss = -__logf(fmaxf(1.f - p_o, 1e-8f)); miss_f = true; }
            }
        }
        __syncthreads();
        if (tid < TILE) {
            const int t = tid;
            if (s_valid[t] && s_valid[t + 1]) {
                const float* pp = (const float*)(sm2 + base2 + t * F2);
                const float* pc = (const float*)(sm2 + base2 + (t + 1) * F2);
                const float invp = s_invs[t];
                float msum = 0.f;
                const int nc = g_ncols;
                for (int j = 0; j < nc; j++) {
                    const int off = g_off[j];
                    const int kk = g_k[j];
                    float acc = 0.f;
                    for (int i = 0; i < kk; i++) acc += pp[g_idx[off + i]];
                    const float term = fmaf(g_sign[j] * invp, acc, g_base[j]);
                    msum = fmaf(pc[g_col[j]], term, msum);
                }
                trans = msum * s_invs[t + 1];
                trans_f = true;
            }
        }
    }

    // -------- block reduction: 4 float sums + 4 popc counts --------
    const unsigned b_ce = __ballot_sync(full, ce_f);
    const unsigned b_ms = __ballot_sync(full, miss_f);
    const unsigned b_fp = __ballot_sync(full, fp_f);
    const unsigned b_tr = __ballot_sync(full, trans_f);
    float sums[4] = {ce, miss, fp, trans};
    #pragma unroll
    for (int k = 0; k < 4; k++) {
        float x = sums[k];
        #pragma unroll
        for (int o = 16; o > 0; o >>= 1) x += __shfl_down_sync(full, x, o);
        sums[k] = x;
    }
    if (lane == 0) {
        s_red[warp * 8 + 0] = sums[0];
        s_red[warp * 8 + 1] = (float)__popc(b_ce);
        s_red[warp * 8 + 2] = sums[1];
        s_red[warp * 8 + 3] = (float)__popc(b_ms);
        s_red[warp * 8 + 4] = sums[2];
        s_red[warp * 8 + 5] = (float)__popc(b_fp);
        s_red[warp * 8 + 6] = sums[3];
        s_red[warp * 8 + 7] = (float)__popc(b_tr);
    }
    __syncthreads();
    if (tid == 0) {
        #pragma unroll
        for (int k = 0; k < 8; k++) {
            float a = 0.f;
            #pragma unroll
            for (int w = 0; w < NWARPS; w++) a += s_red[w * 8 + k];
            g_partials[blockIdx.x * 8 + k] = a;
        }
        __threadfence();
        unsigned int t = atomicAdd(&g_ticket, 1u);
        s_islast = (t == (unsigned int)(nblocks - 1)) ? 1 : 0;
    }
    __syncthreads();

    // -------- last block: deterministic final reduction + output --------
    if (s_islast) {
        float acc[8] = {0.f, 0.f, 0.f, 0.f, 0.f, 0.f, 0.f, 0.f};
        for (int i = tid; i < nblocks; i += TDIM) {
            #pragma unroll
            for (int k = 0; k < 8; k++) acc[k] += g_partials[i * 8 + k];
        }
        #pragma unroll
        for (int k = 0; k < 8; k++) {
            float x = acc[k];
            #pragma unroll
            for (int o = 16; o > 0; o >>= 1) x += __shfl_down_sync(full, x, o);
            acc[k] = x;
        }
        if (lane == 0) {
            #pragma unroll
            for (int k = 0; k < 8; k++) s_red[warp * 8 + k] = acc[k];
        }
        __syncthreads();
        if (tid == 0) {
            float r[8];
            #pragma unroll
            for (int k = 0; k < 8; k++) {
                float a = 0.f;
                #pragma unroll
                for (int w = 0; w < NWARPS; w++) a += s_red[w * 8 + k];
                r[k] = a;
            }
            const float cem   = r[0] / fmaxf(r[1], 1.f);
            const float missm = r[2] / fmaxf(r[3], 1.f);
            const float fpm   = r[4] / fmaxf(r[5], 1.f);
            const float trm   = r[6] / fmaxf(r[7], 1.f);
            out[0] = cem + 1.2f * missm + 1.0f * fpm + 0.8f * trm;
        }
    }
}

// ---------------- launch ----------------
extern "C" void kernel_launch(void* const* d_in, const int* in_sizes, int n_in,
                              void* d_out, int out_size) {
    const float* logits = (const float*)d_in[0];
    const int* labels = (const int*)d_in[1];
    const float* mask = (const float*)d_in[2];

    const int BT = in_sizes[1];
    const int T = 4096;
    const int B = BT / T;
    const int chunks = T / TILE;
    const int nblocks = B * chunks;   // 2048

    build_desc_kernel<<<1, 256>>>(mask);
    ner_main_kernel<<<nblocks, TDIM>>>(logits, labels, (float*)d_out, T, nblocks);
}

// round 15
// speedup vs baseline: 1.3398x; 1.1845x over previous
#include <cuda_runtime.h>

#define C 38
#define PAD_IDX 0
#define O_IDX 1
#define TILE 256
#define ROWS 257
#define TDIM 288          // warps 0..7: 32 rows each; warp 8: row 256 + boundary pairs
#define NWARPS 9
#define F2 19             // 38 floats = 19 float2
#define NPAIR 18
#define RBYTES (C * 4)    // 152 bytes per row
#define LOG2E 1.44269504088896f

// ---------------- device-global scratch (no allocations allowed) ----------------
__device__ float g_partials[8 * 2048];
__device__ unsigned int g_ticket;     // monotonic; last block = (t % nblocks)==nblocks-1

// packed (v.x*log2e, v.y*log2e) in one f32x2 mul
__device__ __forceinline__ float2 mul2_log2e(const float2* p) {
    unsigned long long v = *(const unsigned long long*)p;
    unsigned long long r;
    asm("mul.rn.f32x2 %0, %1, %2;" : "=l"(r)
        : "l"(v), "l"(0x3FB8AA3B3FB8AA3BULL));
    float2 o;
    asm("mov.b64 {%0,%1}, %2;" : "=f"(o.x), "=f"(o.y) : "l"(r));
    return o;
}

// ---------------- single fused kernel ----------------
__global__ void __launch_bounds__(TDIM, 5) ner_main_kernel(
    const float* __restrict__ logits, const int* __restrict__ labels,
    const float* __restrict__ mask, float* __restrict__ out,
    int T, int nblocks) {
    __shared__ __align__(16) float2 sm2[ROWS * F2 + 4];  // packed tile + pad slack
    __shared__ __align__(8) unsigned long long s_mb[NWARPS];
    __shared__ float s_tail_ps[8][NPAIR];        // lane-31 pairsums per primary warp
    __shared__ float s_tail_inv[8];
    __shared__ unsigned char s_tail_val[8];
    __shared__ float s_head_inv[9];              // lane-0 invs (rows 32m, 256)
    __shared__ unsigned char s_head_val[9];
    __shared__ float s_red[NWARPS * 8];
    __shared__ int s_islast;
    __shared__ float s_invs[ROWS];               // fallback only
    __shared__ unsigned char s_valid[ROWS];      // fallback only

    const int tid = threadIdx.x;
    const int warp = tid >> 5, lane = tid & 31;
    const int chunks = T / TILE;
    const int b = blockIdx.x / chunks;
    const int chunk = blockIdx.x % chunks;
    const int start = chunk * TILE;
    const bool has_prev = (chunk > 0);
    const int row0 = has_prev ? 0 : 1;
    const unsigned full = 0xffffffffu;
    const unsigned smb = (unsigned)__cvta_generic_to_shared(sm2);

    // ---- per-warp bulk DMA: warp w stages only its own rows ----
    const long long baserow = (long long)b * T + start - 1;   // logical row 0
    const unsigned pad0 = (unsigned)(((unsigned long long)(const char*)logits +
                                      (unsigned long long)(baserow * RBYTES)) & 15ull);
    int rb, nrows;
    if (warp < 8) {
        rb = 32 * warp; nrows = 32;
        if (warp == 0 && !has_prev) { rb = 1; nrows = 31; }
    } else { rb = 256; nrows = 1; }
    const char* src = (const char*)logits + (baserow + rb) * (long long)RBYTES;
    const unsigned padw = (unsigned)((unsigned long long)src & 15ull);
    const unsigned dst = smb + (unsigned)(rb * RBYTES) + pad0 - padw;   // 16B aligned
    const unsigned size = (padw + (unsigned)(nrows * RBYTES) + 15u) & ~15u;
    const unsigned mb = (unsigned)__cvta_generic_to_shared(&s_mb[warp]);

    if (lane == 0)
        asm volatile("mbarrier.init.shared.b64 [%0], 1;" :: "r"(mb) : "memory");
    __syncwarp();
    if (lane == 0) {
        asm volatile("mbarrier.arrive.expect_tx.shared.b64 _, [%0], %1;"
                     :: "r"(mb), "r"(size) : "memory");
        asm volatile(
            "cp.async.bulk.shared::cluster.global.mbarrier::complete_tx::bytes "
            "[%0], [%1], %2, [%3];"
            :: "r"(dst), "l"(src - padw), "r"(size), "r"(mb) : "memory");
    }

    // ---- canonical-mask detection, overlapped with the DMA ----
    // valid(p,c): c==PAD || c==O || c even (B-) -> 1 ; c odd>=3 (I-X) -> p in {c-1,c}
    bool okl = true;
    #pragma unroll
    for (int u = 0; u < 6; u++) {
        const int i = tid + u * TDIM;
        if (i < C * C) {
            const int p = i / C, c = i - p * C;
            const bool expect = !((c & 1) && c >= 3) || (p == c - 1) || (p == c);
            okl &= ((__ldg(mask + i) >= 0.5f) == expect);
        }
    }
    const int spec2 = __syncthreads_and(okl);

    // row assignment + label prefetch while the DMA is in flight
    int prow;
    if (spec2) prow = (warp < 8) ? (warp * 32 + lane) : ((lane == 0) ? 256 : -1);
    else       prow = (tid < ROWS) ? tid : -1;
    const bool row_ok = (prow >= 0) && (has_prev || prow >= 1);
    int label = PAD_IDX;
    if (row_ok) label = __ldg(labels + (long long)b * T + (start - 1 + prow));

    // wait for OWN slice only (HW-sleep try_wait, phase parity 0)
    asm volatile(
        "{\n\t.reg .pred P;\n\t"
        "W%=: mbarrier.try_wait.parity.shared.b64 P, [%0], 0;\n\t"
        "@P bra D%=;\n\t"
        "bra W%=;\n\t"
        "D%=:\n\t}" :: "r"(mb) : "memory");

    // logical row r lives at sm2 + base2 + r*F2
    const int base2 = (int)(pad0 >> 3);

    float ce = 0.f, miss = 0.f, fp = 0.f, trans = 0.f;
    bool ce_f = false, miss_f = false, fp_f = false, trans_f = false;

    if (spec2) {
        // ================= fused fast path (ubase=1, usign=-1) =================
        if (warp < 8) {
            const int rs = row_ok ? prow : row0;   // staged row (safe for shuffles)
            const float2* row2 = sm2 + base2 + rs * F2;
            const bool valid = row_ok && (label != PAD_IDX);
            const float gold_l = ((const float*)row2)[label];

            float2 e = mul2_log2e(row2);
            const float e00 = exp2f(e.x);
            const float eO  = exp2f(e.y);          // O_IDX == 1
            float s0 = e00 + eO, s1 = 0.f, A = 0.f, B = 0.f;
            const bool tail = (lane == 31);
            #pragma unroll
            for (int k = 1; k < F2; k++) {
                e = mul2_log2e(row2 + k);
                const float e0 = exp2f(e.x);
                const float e1 = exp2f(e.y);
                const float ps = e0 + e1;
                if (k & 1) s1 += ps; else s0 += ps;
                if (tail) s_tail_ps[warp][k - 1] = ps;
                const float e1n = __shfl_down_sync(full, e1, 1);
                A += e1n;
                B = fmaf(e1n, ps, B);
            }
            const float s = s0 + s1;
            const float invs = 1.f / s;
            if (tail)      { s_tail_inv[warp] = invs; s_tail_val[warp] = valid; }
            if (lane == 0) { s_head_inv[warp] = invs; s_head_val[warp] = valid; }

            const unsigned vb = __ballot_sync(full, valid);
            const float invc = __shfl_down_sync(full, invs, 1);

            if (valid && prow >= 1) {              // CE for tokens start..start+254
                ce = __logf(s) - gold_l; ce_f = true;
                const float p_o = eO * invs;
                if (label == O_IDX) { fp = -__logf(fmaxf(p_o, 1e-8f)); fp_f = true; }
                else { miss = -__logf(fmaxf(1.f - p_o, 1e-8f)); miss_f = true; }
            }
            if (lane < 31 && valid && ((vb >> (lane + 1)) & 1u)) {
                trans = invc * fmaf(-invs, B, A);   // invc*(A - invp*B)
                trans_f = true;
            }
        } else if (lane == 0) {
            // warp 8 lane 0: row 256 softmax (token start+255)
            const float2* row2 = sm2 + base2 + 256 * F2;
            const bool valid = (label != PAD_IDX);
            const float gold_l = ((const float*)row2)[label];
            float s0 = 0.f, s1 = 0.f, eO = 0.f;
            #pragma unroll
            for (int k = 0; k < F2; k++) {
                float2 e = mul2_log2e(row2 + k);
                const float a0 = exp2f(e.x), a1 = exp2f(e.y);
                if (k == 0) eO = a1;
                s0 += a0; s1 += a1;
            }
            const float s = s0 + s1;
            const float invs = 1.f / s;
            s_head_inv[8] = invs; s_head_val[8] = valid;
            if (valid) {
                ce = __logf(s) - gold_l; ce_f = true;
                const float p_o = eO * invs;
                if (label == O_IDX) { fp = -__logf(fmaxf(p_o, 1e-8f)); fp_f = true; }
                else { miss = -__logf(fmaxf(1.f - p_o, 1e-8f)); miss_f = true; }
            }
        }
        __syncthreads();                           // stashes + all slices visible
        // boundary pairs (32m-1, 32m), m=1..8 — warp 8 lanes 1..8
        if (warp == 8 && lane >= 1 && lane <= 8) {
            const int m = lane;
            if (s_head_val[m] && s_tail_val[m - 1]) {
                const float2* r2 = sm2 + base2 + (32 * m) * F2;
                float A2 = 0.f, B2 = 0.f;
                #pragma unroll
                for (int k = 1; k < F2; k++) {
                    float2 e = mul2_log2e(r2 + k);
                    const float e1 = exp2f(e.y);
                    A2 += e1;
                    B2 = fmaf(e1, s_tail_ps[m - 1][k - 1], B2);
                }
                trans = s_head_inv[m] * fmaf(-s_tail_inv[m - 1], B2, A2);
                trans_f = true;
            }
        }
    } else {
        // ============ general fallback: correct for any mask (slow path) ============
        __syncthreads();       // every warp waited its own barrier -> all DMAs done
        if (!has_prev && tid == 0) s_valid[0] = 0;
        if (row_ok) {
            const int r = prow;
            float2* row2 = sm2 + base2 + r * F2;
            s_valid[r] = (unsigned char)(label != PAD_IDX);
            const float gold_l = ((const float*)row2)[label];
            float2 v = row2[0];
            const float e0a = exp2f(v.x * LOG2E);
            const float eO = exp2f(v.y * LOG2E);
            float s0 = e0a + eO, s1 = 0.f;
            #pragma unroll
            for (int k = 1; k < F2; k++) {
                v = row2[k];
                const float e0 = exp2f(v.x * LOG2E);
                const float e1 = exp2f(v.y * LOG2E);
                if (k & 1) s1 += e0 + e1; else s0 += e0 + e1;
                row2[k] = make_float2(e0, e1);
            }
            row2[0] = make_float2(e0a, eO);
            const float s = s0 + s1;
            const float invs = 1.f / s;
            s_invs[r] = invs;
            if (r >= 1 && label != PAD_IDX) {
                ce = (__logf(s) - gold_l); ce_f = true;
                const float p_o = eO * invs;
                if (label == O_IDX) { fp = -__logf(fmaxf(p_o, 1e-8f)); fp_f = true; }
                else { miss = -__logf(fmaxf(1.f - p_o, 1e-8f)); miss_f = true; }
            }
        }
        __syncthreads();
        if (tid < TILE) {
            const int t = tid;
            if (s_valid[t] && s_valid[t + 1]) {
                const float* pp = (const float*)(sm2 + base2 + t * F2);
                const float* pc = (const float*)(sm2 + base2 + (t + 1) * F2);
                float msum = 0.f;
                for (int p = 0; p < C; p++) {
                    const float ppv = pp[p];
                    for (int c = 0; c < C; c++)
                        if (__ldg(mask + p * C + c) < 0.5f)
                            msum = fmaf(ppv, pc[c], msum);
                }
                trans = msum * s_invs[t] * s_invs[t + 1];
                trans_f = true;
            }
        }
    }

    // -------- block reduction: 4 float sums + 4 popc counts --------
    const unsigned b_ce = __ballot_sync(full, ce_f);
    const unsigned b_ms = __ballot_sync(full, miss_f);
    const unsigned b_fp = __ballot_sync(full, fp_f);
    const unsigned b_tr = __ballot_sync(full, trans_f);
    float sums[4] = {ce, miss, fp, trans};
    #pragma unroll
    for (int k = 0; k < 4; k++) {
        float x = sums[k];
        #pragma unroll
        for (int o = 16; o > 0; o >>= 1) x += __shfl_down_sync(full, x, o);
        sums[k] = x;
    }
    if (lane == 0) {
        s_red[warp * 8 + 0] = sums[0];
        s_red[warp * 8 + 1] = (float)__popc(b_ce);
        s_red[warp * 8 + 2] = sums[1];
        s_red[warp * 8 + 3] = (float)__popc(b_ms);
        s_red[warp * 8 + 4] = sums[2];
        s_red[warp * 8 + 5] = (float)__popc(b_fp);
        s_red[warp * 8 + 6] = sums[3];
        s_red[warp * 8 + 7] = (float)__popc(b_tr);
    }
    __syncthreads();
    if (tid == 0) {
        #pragma unroll
        for (int k = 0; k < 8; k++) {
            float a = 0.f;
            #pragma unroll
            for (int w = 0; w < NWARPS; w++) a += s_red[w * 8 + k];
            g_partials[blockIdx.x * 8 + k] = a;
        }
        __threadfence();
        const unsigned t = atomicAdd(&g_ticket, 1u);
        s_islast = ((t % (unsigned)nblocks) == (unsigned)(nblocks - 1)) ? 1 : 0;
    }
    __syncthreads();

    // -------- last block: deterministic final reduction + output --------
    if (s_islast) {
        float acc[8] = {0.f, 0.f, 0.f, 0.f, 0.f, 0.f, 0.f, 0.f};
        for (int i = tid; i < nblocks; i += TDIM) {
            #pragma unroll
            for (int k = 0; k < 8; k++) acc[k] += g_partials[i * 8 + k];
        }
        #pragma unroll
        for (int k = 0; k < 8; k++) {
            float x = acc[k];
            #pragma unroll
            for (int o = 16; o > 0; o >>= 1) x += __shfl_down_sync(full, x, o);
            acc[k] = x;
        }
        if (lane == 0) {
            #pragma unroll
            for (int k = 0; k < 8; k++) s_red[warp * 8 + k] = acc[k];
        }
        __syncthreads();
        if (tid == 0) {
            float r[8];
            #pragma unroll
            for (int k = 0; k < 8; k++) {
                float a = 0.f;
                #pragma unroll
                for (int w = 0; w < NWARPS; w++) a += s_red[w * 8 + k];
                r[k] = a;
            }
            const float cem   = r[0] / fmaxf(r[1], 1.f);
            const float missm = r[2] / fmaxf(r[3], 1.f);
            const float fpm   = r[4] / fmaxf(r[5], 1.f);
            const float trm   = r[6] / fmaxf(r[7], 1.f);
            out[0] = cem + 1.2f * missm + 1.0f * fpm + 0.8f * trm;
        }
    }
}

// ---------------- launch: single kernel ----------------
extern "C" void kernel_launch(void* const* d_in, const int* in_sizes, int n_in,
                              void* d_out, int out_size) {
    const float* logits = (const float*)d_in[0];
    const int* labels = (const int*)d_in[1];
    const float* mask = (const float*)d_in[2];

    const int BT = in_sizes[1];
    const int T = 4096;
    const int B = BT / T;
    const int chunks = T / TILE;
    const int nblocks = B * chunks;   // 2048

    ner_main_kernel<<<nblocks, TDIM>>>(logits, labels, mask, (float*)d_out,
                                       T, nblocks);
}

// round 17
// speedup vs baseline: 1.4010x; 1.0457x over previous
#include <cuda_runtime.h>

#define C 38
#define PAD_IDX 0
#define O_IDX 1
#define TILE 128
#define ROWS 129
#define TDIM 160          // warps 0..3: 32 rows each; warp 4: row 128 + boundary pairs
#define NWARPS 5
#define NPRIM 4
#define F2 19             // 38 floats = 19 float2
#define BUF2 (ROWS * F2 + 5)   // 2456 float2 = 19648 B: keeps BOTH buffers 16B-aligned
#define NPAIR 18
#define RBYTES (C * 4)    // 152 bytes per row
#define LOG2E 1.44269504088896f
#define MAXBLK 740        // 148 SMs x 5 CTAs

// ---------------- device-global scratch (no allocations allowed) ----------------
__device__ float g_partials[8 * MAXBLK];
__device__ unsigned int g_ticket;     // monotonic; last block = (t % nblk)==nblk-1

// packed (v.x*log2e, v.y*log2e) in one f32x2 mul
__device__ __forceinline__ float2 mul2_log2e(const float2* p) {
    unsigned long long v = *(const unsigned long long*)p;
    unsigned long long r;
    asm("mul.rn.f32x2 %0, %1, %2;" : "=l"(r)
        : "l"(v), "l"(0x3FB8AA3B3FB8AA3BULL));
    float2 o;
    asm("mov.b64 {%0,%1}, %2;" : "=f"(o.x), "=f"(o.y) : "l"(r));
    return o;
}

// per-warp bulk-DMA slice of one tile into buffer smbuf, completing on mb
__device__ __forceinline__ void issue_slice(const float* logits, long long baserow,
                                            bool has_prev, int warp,
                                            unsigned smbuf, unsigned mb) {
    int rb, nrows;
    if (warp < NPRIM) {
        rb = 32 * warp; nrows = 32;
        if (warp == 0 && !has_prev) { rb = 1; nrows = 31; }
    } else { rb = TILE; nrows = 1; }
    const char* src = (const char*)logits + (baserow + rb) * (long long)RBYTES;
    const unsigned pad0 = (unsigned)(((unsigned long long)(const char*)logits +
                          (unsigned long long)(baserow * RBYTES)) & 15ull);
    const unsigned padw = (unsigned)((unsigned long long)src & 15ull);
    const unsigned dst = smbuf + (unsigned)(rb * RBYTES) + pad0 - padw;  // 16B aligned
    const unsigned size = (padw + (unsigned)(nrows * RBYTES) + 15u) & ~15u;
    asm volatile("mbarrier.arrive.expect_tx.shared.b64 _, [%0], %1;"
                 :: "r"(mb), "r"(size) : "memory");
    asm volatile(
        "cp.async.bulk.shared::cluster.global.mbarrier::complete_tx::bytes "
        "[%0], [%1], %2, [%3];"
        :: "r"(dst), "l"(src - padw), "r"(size), "r"(mb) : "memory");
}

__device__ __forceinline__ void mbar_wait(unsigned mb, int ph) {
    asm volatile(
        "{\n\t.reg .pred P;\n\t"
        "W%=: mbarrier.try_wait.parity.shared.b64 P, [%0], %1;\n\t"
        "@P bra D%=;\n\t"
        "bra W%=;\n\t"
        "D%=:\n\t}" :: "r"(mb), "r"(ph) : "memory");
}

// ---------------- single persistent fused kernel ----------------
__global__ void __launch_bounds__(TDIM, 5) ner_main_kernel(
    const float* __restrict__ logits, const int* __restrict__ labels,
    const float* __restrict__ mask, float* __restrict__ out,
    int T, int ntiles, int nblk) {
    __shared__ __align__(16) float2 sm2[2][BUF2];            // double-buffered tile
    __shared__ __align__(8) unsigned long long s_mb[2][NWARPS];
    __shared__ float s_tail_ps[2][NPRIM][NPAIR];   // lane-31 pairsums
    __shared__ float s_tail_inv[2][NPRIM];
    __shared__ unsigned char s_tail_val[2][NPRIM];
    __shared__ float s_head_e1[2][NPRIM][NPAIR];   // head-row e_odd (rows 32,64,96,128)
    __shared__ float s_head_inv[2][NPRIM];
    __shared__ unsigned char s_head_val[2][NPRIM];
    __shared__ float s_red[NWARPS * 8];
    __shared__ int s_islast;
    __shared__ float s_invs[ROWS];                 // fallback only
    __shared__ unsigned char s_valid[ROWS];        // fallback only

    const int tid = threadIdx.x;
    const int warp = tid >> 5, lane = tid & 31;
    const int bid = blockIdx.x;
    const int chunks = T / TILE;
    const unsigned full = 0xffffffffu;
    const unsigned smb0 = (unsigned)__cvta_generic_to_shared(sm2[0]);
    const unsigned smb1 = (unsigned)__cvta_generic_to_shared(sm2[1]);
    const unsigned mba0 = (unsigned)__cvta_generic_to_shared(&s_mb[0][warp]);
    const unsigned mba1 = (unsigned)__cvta_generic_to_shared(&s_mb[1][warp]);

    const int ntm = (ntiles - bid + nblk - 1) / nblk;   // tiles for this block

    // init this warp's two mbarriers, then prologue DMAs for iters 0 and 1
    if (lane == 0) {
        asm volatile("mbarrier.init.shared.b64 [%0], 1;" :: "r"(mba0) : "memory");
        asm volatile("mbarrier.init.shared.b64 [%0], 1;" :: "r"(mba1) : "memory");
    }
    __syncwarp();
    if (lane == 0 && ntm > 0) {
        const int tile = bid;
        const int ch = tile % chunks;
        issue_slice(logits,
                    (long long)(tile / chunks) * T + ch * TILE - 1,
                    ch > 0, warp, smb0, mba0);
    }
    if (lane == 0 && ntm > 1) {
        const int tile = bid + nblk;
        const int ch = tile % chunks;
        issue_slice(logits,
                    (long long)(tile / chunks) * T + ch * TILE - 1,
                    ch > 0, warp, smb1, mba1);
    }

    // canonical-mask detection (once per block), overlapped with the DMAs
    // valid(p,c): c==PAD || c==O || c even (B-) -> 1 ; c odd>=3 (I-X) -> p in {c-1,c}
    bool okl = true;
    #pragma unroll
    for (int u = 0; u < 10; u++) {
        const int i = tid + u * TDIM;
        if (i < C * C) {
            const int p = i / C, c = i - p * C;
            const bool expect = !((c & 1) && c >= 3) || (p == c - 1) || (p == c);
            okl &= ((__ldg(mask + i) >= 0.5f) == expect);
        }
    }
    const int spec2 = __syncthreads_and(okl);

    float ce = 0.f, miss = 0.f, fp = 0.f, trans = 0.f;
    float ce_c = 0.f, ms_c = 0.f, fp_c = 0.f, tr_c = 0.f;

    // =================== persistent tile loop ===================
    for (int it = 0; it < ntm; it++) {
        const int tile = bid + it * nblk;
        const int s = it & 1;
        const int ph = (it >> 1) & 1;
        const int b = tile / chunks;
        const int chunk = tile - b * chunks;
        const int start = chunk * TILE;
        const bool has_prev = (chunk > 0);
        const long long baserow = (long long)b * T + start - 1;
        const unsigned pad0 = (unsigned)(((unsigned long long)(const char*)logits +
                              (unsigned long long)(baserow * RBYTES)) & 15ull);
        const int base2 = (int)(pad0 >> 3);
        const float2* buf = sm2[s] + base2;
        const unsigned mba = s ? mba1 : mba0;
        const unsigned smb = s ? smb1 : smb0;

        // row assignment + label prefetch (before the wait)
        int prow;
        if (spec2) prow = (warp < NPRIM) ? (warp * 32 + lane)
                                         : ((lane == 0) ? TILE : -1);
        else       prow = (tid < ROWS) ? tid : -1;
        const bool row_ok = (prow >= 0) && (has_prev || prow >= 1);
        int label = PAD_IDX;
        if (row_ok) label = __ldg(labels + (long long)b * T + (start - 1 + prow));

        mbar_wait(mba, ph);                        // own slice only

        if (spec2) {
            // ---------------- fused fast path ----------------
            if (warp < NPRIM) {
                const int rs = row_ok ? prow : 1;  // shuffle-safe staged row
                const float2* row2 = buf + rs * F2;
                const bool valid = row_ok && (label != PAD_IDX);
                const float gold_l = ((const float*)row2)[label];

                float2 e = mul2_log2e(row2);
                const float e00 = exp2f(e.x);
                const float eO  = exp2f(e.y);      // O_IDX == 1
                float s0 = e00 + eO, s1 = 0.f, A = 0.f, B = 0.f;
                const bool tail = (lane == 31);
                const bool head = (lane == 0) && (warp >= 1);
                #pragma unroll
                for (int k = 1; k < F2; k++) {
                    e = mul2_log2e(row2 + k);
                    const float e0 = exp2f(e.x);
                    const float e1 = exp2f(e.y);
                    const float ps = e0 + e1;
                    if (k & 1) s1 += ps; else s0 += ps;
                    if (tail) s_tail_ps[s][warp][k - 1] = ps;
                    if (head) s_head_e1[s][warp - 1][k - 1] = e1;
                    const float e1n = __shfl_down_sync(full, e1, 1);
                    A += e1n;
                    B = fmaf(e1n, ps, B);
                }
                const float sm = s0 + s1;
                const float invs = 1.f / sm;
                if (tail) { s_tail_inv[s][warp] = invs; s_tail_val[s][warp] = valid; }
                if (head) { s_head_inv[s][warp - 1] = invs;
                            s_head_val[s][warp - 1] = valid; }

                const unsigned vb = __ballot_sync(full, valid);
                const float invc = __shfl_down_sync(full, invs, 1);

                if (valid && prow >= 1) {
                    ce += __logf(sm) - gold_l; ce_c += 1.f;
                    const float p_o = eO * invs;
                    if (label == O_IDX) { fp += -__logf(fmaxf(p_o, 1e-8f)); fp_c += 1.f; }
                    else { miss += -__logf(fmaxf(1.f - p_o, 1e-8f)); ms_c += 1.f; }
                }
                if (lane < 31 && valid && ((vb >> (lane + 1)) & 1u)) {
                    trans += invc * fmaf(-invs, B, A);   // invc*(A - invp*B)
                    tr_c += 1.f;
                }
            } else if (lane == 0) {
                // warp 4 lane 0: row TILE softmax (token start+TILE-1)
                const float2* row2 = buf + TILE * F2;
                const bool valid = (label != PAD_IDX);
                const float gold_l = ((const float*)row2)[label];
                float s0 = 0.f, s1 = 0.f, eO = 0.f;
                #pragma unroll
                for (int k = 0; k < F2; k++) {
                    float2 e = mul2_log2e(row2 + k);
                    const float a0 = exp2f(e.x), a1 = exp2f(e.y);
                    if (k == 0) eO = a1;
                    else s_head_e1[s][NPRIM - 1][k - 1] = a1;
                    s0 += a0; s1 += a1;
                }
                const float sm = s0 + s1;
                const float invs = 1.f / sm;
                s_head_inv[s][NPRIM - 1] = invs;
                s_head_val[s][NPRIM - 1] = valid;
                if (valid) {
                    ce += __logf(sm) - gold_l; ce_c += 1.f;
                    const float p_o = eO * invs;
                    if (label == O_IDX) { fp += -__logf(fmaxf(p_o, 1e-8f)); fp_c += 1.f; }
                    else { miss += -__logf(fmaxf(1.f - p_o, 1e-8f)); ms_c += 1.f; }
                }
            }
            __syncthreads();                       // buffer s fully consumed

            // reissue this buffer for iter+2 (pipeline depth 2)
            if (lane == 0 && it + 2 < ntm) {
                const int ntile = bid + (it + 2) * nblk;
                const int nch = ntile % chunks;
                issue_slice(logits,
                            (long long)(ntile / chunks) * T + nch * TILE - 1,
                            nch > 0, warp, smb, mba);
            }
            // boundary pairs (32m-1, 32m), m=1..4 — from stashes only
            if (warp == NPRIM && lane >= 1 && lane <= NPRIM) {
                const int m = lane - 1;
                if (s_head_val[s][m] && s_tail_val[s][m]) {
                    float A2 = 0.f, B2 = 0.f;
                    #pragma unroll
                    for (int k = 0; k < NPAIR; k++) {
                        const float e1 = s_head_e1[s][m][k];
                        A2 += e1;
                        B2 = fmaf(e1, s_tail_ps[s][m][k], B2);
                    }
                    trans += s_head_inv[s][m] * fmaf(-s_tail_inv[s][m], B2, A2);
                    tr_c += 1.f;
                }
            }
        } else {
            // ---------------- general fallback (any mask) ----------------
            __syncthreads();                       // all slices of this tile landed
            if (!has_prev && tid == 0) s_valid[0] = 0;
            if (row_ok) {
                const int r = prow;
                float2* row2 = (float2*)(buf + r * F2);
                s_valid[r] = (unsigned char)(label != PAD_IDX);
                const float gold_l = ((const float*)row2)[label];
                float2 v = row2[0];
                const float e0a = exp2f(v.x * LOG2E);
                const float eO = exp2f(v.y * LOG2E);
                float s0 = e0a + eO, s1 = 0.f;
                #pragma unroll
                for (int k = 1; k < F2; k++) {
                    v = row2[k];
                    const float e0 = exp2f(v.x * LOG2E);
                    const float e1 = exp2f(v.y * LOG2E);
                    if (k & 1) s1 += e0 + e1; else s0 += e0 + e1;
                    row2[k] = make_float2(e0, e1);
                }
                row2[0] = make_float2(e0a, eO);
                const float sm = s0 + s1;
                const float invs = 1.f / sm;
                s_invs[r] = invs;
                if (r >= 1 && label != PAD_IDX) {
                    ce += (__logf(sm) - gold_l); ce_c += 1.f;
                    const float p_o = eO * invs;
                    if (label == O_IDX) { fp += -__logf(fmaxf(p_o, 1e-8f)); fp_c += 1.f; }
                    else { miss += -__logf(fmaxf(1.f - p_o, 1e-8f)); ms_c += 1.f; }
                }
            }
            __syncthreads();
            if (tid < TILE && s_valid[tid] && s_valid[tid + 1]) {
                const float* pp = (const float*)(buf + tid * F2);
                const float* pc = (const float*)(buf + (tid + 1) * F2);
                float msum = 0.f;
                for (int p = 0; p < C; p++) {
                    const float ppv = pp[p];
                    for (int c = 0; c < C; c++)
                        if (__ldg(mask + p * C + c) < 0.5f)
                            msum = fmaf(ppv, pc[c], msum);
                }
                trans += msum * s_invs[tid] * s_invs[tid + 1];
                tr_c += 1.f;
            }
            __syncthreads();                       // buffer reads done before reissue
            if (lane == 0 && it + 2 < ntm) {
                const int ntile = bid + (it + 2) * nblk;
                const int nch = ntile % chunks;
                issue_slice(logits,
                            (long long)(ntile / chunks) * T + nch * TILE - 1,
                            nch > 0, warp, smb, mba);
            }
        }
    }

    // =================== final block reduction ===================
    float sums[8] = {ce, ce_c, miss, ms_c, fp, fp_c, trans, tr_c};
    #pragma unroll
    for (int k = 0; k < 8; k++) {
        float x = sums[k];
        #pragma unroll
        for (int o = 16; o > 0; o >>= 1) x += __shfl_down_sync(full, x, o);
        sums[k] = x;
    }
    if (lane == 0) {
        #pragma unroll
        for (int k = 0; k < 8; k++) s_red[warp * 8 + k] = sums[k];
    }
    __syncthreads();
    if (tid == 0) {
        #pragma unroll
        for (int k = 0; k < 8; k++) {
            float a = 0.f;
            #pragma unroll
            for (int w = 0; w < NWARPS; w++) a += s_red[w * 8 + k];
            g_partials[bid * 8 + k] = a;
        }
        __threadfence();
        const unsigned t = atomicAdd(&g_ticket, 1u);
        s_islast = ((t % (unsigned)nblk) == (unsigned)(nblk - 1)) ? 1 : 0;
    }
    __syncthreads();

    if (s_islast) {
        float acc[8] = {0.f, 0.f, 0.f, 0.f, 0.f, 0.f, 0.f, 0.f};
        for (int i = tid; i < nblk; i += TDIM) {
            #pragma unroll
            for (int k = 0; k < 8; k++) acc[k] += g_partials[i * 8 + k];
        }
        #pragma unroll
        for (int k = 0; k < 8; k++) {
            float x = acc[k];
            #pragma unroll
            for (int o = 16; o > 0; o >>= 1) x += __shfl_down_sync(full, x, o);
            acc[k] = x;
        }
        if (lane == 0) {
            #pragma unroll
            for (int k = 0; k < 8; k++) s_red[warp * 8 + k] = acc[k];
        }
        __syncthreads();
        if (tid == 0) {
            float r[8];
            #pragma unroll
            for (int k = 0; k < 8; k++) {
                float a = 0.f;
                #pragma unroll
                for (int w = 0; w < NWARPS; w++) a += s_red[w * 8 + k];
                r[k] = a;
            }
            const float cem   = r[0] / fmaxf(r[1], 1.f);
            const float missm = r[2] / fmaxf(r[3], 1.f);
            const float fpm   = r[4] / fmaxf(r[5], 1.f);
            const float trm   = r[6] / fmaxf(r[7], 1.f);
            out[0] = cem + 1.2f * missm + 1.0f * fpm + 0.8f * trm;
        }
    }
}

// ---------------- launch: single persistent kernel ----------------
extern "C" void kernel_launch(void* const* d_in, const int* in_sizes, int n_in,
                              void* d_out, int out_size) {
    const float* logits = (const float*)d_in[0];
    const int* labels = (const int*)d_in[1];
    const float* mask = (const float*)d_in[2];

    const int BT = in_sizes[1];
    const int T = 4096;
    const int B = BT / T;
    const int ntiles = B * (T / TILE);            // 4096
    const int nblk = (ntiles < MAXBLK) ? ntiles : MAXBLK;

    ner_main_kernel<<<nblk, TDIM>>>(logits, labels, mask, (float*)d_out,
                                    T, ntiles, nblk);
}